// round 10
// baseline (speedup 1.0000x reference)
#include <cuda_runtime.h>
#include <cuda_bf16.h>
#include <cstdint>
#include <math.h>

#define D_EMBED 128
#define NHEAD   4
#define HD      32
#define NTOK    4096
#define BATCH   4
#define QT      128            // queries per CTA (4 warps x 32 rows)
#define KT      128            // keys per tile
#define NKT     (NTOK / KT)

#define KSTRIDE 40             // bf16 elems per smem row (80B) -> conflict-free ldmatrix
#define QST     136            // qkv smem stride (272B rows) -> conflict-free ldmatrix

// Scratch: [part(q,k,v)][b][head][tok][hd], bf16 (Q pre-scaled by log2e/sqrt(hd))
__device__ __nv_bfloat16 g_qkv[3u * BATCH * NHEAD * NTOK * HD];

// Schraudolph exp2: 2 fixed-lat ops on fma/alu pipes instead of MUFU (rt 8).
// i = (int)(x*2^23 + (127 - 0.0432)*2^23); max rel err ~±3%, mean bias
// cancels in the softmax ratio, residual averages down ~1/sqrt(N_eff).
__device__ __forceinline__ float fast_exp2(float x) {
    int i = (int)fmaf(x, 8388608.0f, 1064990828.0f);
    return __int_as_float(i);
}

__device__ __forceinline__ uint32_t smem_u32(const void* p) {
    uint32_t a;
    asm("{ .reg .u64 t; cvta.to.shared.u64 t, %1; cvt.u32.u64 %0, t; }"
        : "=r"(a) : "l"(p));
    return a;
}

__device__ __forceinline__ uint32_t pack_bf16x2(float lo, float hi) {
    uint32_t r;
    asm("cvt.rn.bf16x2.f32 %0, %1, %2;" : "=r"(r) : "f"(hi), "f"(lo));
    return r;
}

#define CP_ASYNC16(dst, src) \
    asm volatile("cp.async.ca.shared.global [%0], [%1], 16;" \
                 :: "r"(dst), "l"(src) : "memory")
#define CP_COMMIT()  asm volatile("cp.async.commit_group;" ::: "memory")
#define CP_WAIT0()   asm volatile("cp.async.wait_group 0;" ::: "memory")

#define MMA_BF16(d, a, b0, b1)                                              \
    asm volatile(                                                           \
        "mma.sync.aligned.m16n8k16.row.col.f32.bf16.bf16.f32 "              \
        "{%0,%1,%2,%3}, {%4,%5,%6,%7}, {%8,%9}, {%0,%1,%2,%3};"             \
        : "+f"((d)[0]), "+f"((d)[1]), "+f"((d)[2]), "+f"((d)[3])            \
        : "r"((a)[0]), "r"((a)[1]), "r"((a)[2]), "r"((a)[3]),               \
          "r"(b0), "r"(b1))

#define LDM_X4(r, addr)                                                     \
    asm volatile("ldmatrix.sync.aligned.m8n8.x4.shared.b16 "                \
                 "{%0,%1,%2,%3}, [%4];"                                     \
                 : "=r"((r)[0]), "=r"((r)[1]), "=r"((r)[2]), "=r"((r)[3])   \
                 : "r"(addr))

#define LDM_X4_T(r, addr)                                                   \
    asm volatile("ldmatrix.sync.aligned.m8n8.x4.trans.shared.b16 "          \
                 "{%0,%1,%2,%3}, [%4];"                                     \
                 : "=r"((r)[0]), "=r"((r)[1]), "=r"((r)[2]), "=r"((r)[3])   \
                 : "r"(addr))

// ---------------------------------------------------------------------------
// QKV projection with bf16 tensor cores (unchanged from round 9).
// ---------------------------------------------------------------------------
__global__ __launch_bounds__(256) void qkv_mma_kernel(const float* __restrict__ x,
                                                      const float* __restrict__ W,
                                                      const float* __restrict__ bias) {
    __shared__ __nv_bfloat16 As[32][QST];   // [k][token]
    __shared__ __nv_bfloat16 Ws[32][QST];   // [k][col]

    const int tid  = threadIdx.x;
    const int wid  = tid >> 5;
    const int lane = tid & 31;
    const int gid  = lane >> 2;
    const int tig  = lane & 3;
    const int lr   = lane & 7;
    const int lm   = lane >> 3;

    const int m0   = blockIdx.x * 128;
    const int b    = m0 / NTOK;
    const int pix0 = m0 % NTOK;
    const int part = blockIdx.y;
    const int col0 = part * 128;

    const float* xb = x + (size_t)b * D_EMBED * NTOK;

    const int mwarp = 32 * (wid >> 1);
    const int nwarp = 64 * (wid & 1);

    const uint32_t aBase = smem_u32(&As[0][0]);
    const uint32_t wBase = smem_u32(&Ws[0][0]);
    const uint32_t ROWB = QST * 2;
    const uint32_t a_lane = (uint32_t)(lr + 8 * (lm >> 1)) * ROWB
                          + (uint32_t)(8 * (lm & 1)) * 2;
    const uint32_t b_lane = (uint32_t)(lr + 8 * (lm & 1)) * ROWB
                          + (uint32_t)(8 * (lm >> 1)) * 2;

    float oacc[2][8][4] = {};

    for (int kc = 0; kc < 4; kc++) {
        const int k0 = kc * 32;
        __syncthreads();
        #pragma unroll
        for (int i = 0; i < 4; i++) {
            int idx = tid + i * 256;
            int row = idx >> 5, p4 = idx & 31;
            float4 xa = *(const float4*)(xb + (size_t)(k0 + row) * NTOK + pix0 + 4 * p4);
            float4 wa = *(const float4*)(W + (size_t)(k0 + row) * 384 + col0 + 4 * p4);
            uint2 xv = { pack_bf16x2(xa.x, xa.y), pack_bf16x2(xa.z, xa.w) };
            uint2 wv = { pack_bf16x2(wa.x, wa.y), pack_bf16x2(wa.z, wa.w) };
            *(uint2*)&As[row][4 * p4] = xv;
            *(uint2*)&Ws[row][4 * p4] = wv;
        }
        __syncthreads();

        #pragma unroll
        for (int s = 0; s < 2; s++) {
            uint32_t aF[2][4];
            #pragma unroll
            for (int r = 0; r < 2; r++)
                LDM_X4_T(aF[r], aBase + a_lane + (uint32_t)(16 * s) * ROWB
                                 + (uint32_t)(mwarp + 16 * r) * 2);
            #pragma unroll
            for (int g2 = 0; g2 < 4; g2++) {
                uint32_t bF[4];
                LDM_X4_T(bF, wBase + b_lane + (uint32_t)(16 * s) * ROWB
                               + (uint32_t)(nwarp + 16 * g2) * 2);
                #pragma unroll
                for (int r = 0; r < 2; r++) {
                    MMA_BF16(oacc[r][2 * g2],     aF[r], bF[0], bF[1]);
                    MMA_BF16(oacc[r][2 * g2 + 1], aF[r], bF[2], bF[3]);
                }
            }
        }
    }

    const float qs = (part == 0) ? 0.17677669529663687f * 1.4426950408889634f : 1.0f;
    #pragma unroll
    for (int r = 0; r < 2; r++) {
        const int tok = pix0 + mwarp + 16 * r + gid;
        #pragma unroll
        for (int nt = 0; nt < 8; nt++) {
            const int col = nwarp + nt * 8 + 2 * tig;
            const int head = col >> 5;
            const int d    = col & 31;
            const float bx = bias[col0 + col];
            const float by = bias[col0 + col + 1];
            __nv_bfloat16* dst =
                g_qkv + ((((size_t)part * BATCH + b) * NHEAD + head) * NTOK + tok) * HD + d;
            *(uint32_t*)dst =
                pack_bf16x2((oacc[r][nt][0] + bx) * qs, (oacc[r][nt][1] + by) * qs);
            *(uint32_t*)(dst + 8 * HD) =
                pack_bf16x2((oacc[r][nt][2] + bx) * qs, (oacc[r][nt][3] + by) * qs);
        }
    }
}

// ---------------------------------------------------------------------------
// Flash attention, bf16 mma.m16n8k16 + ldmatrix + cp.async double buffering.
// 4 warps x 32 query rows; 128-key tiles (32 iterations); Schraudolph exp2
// on fma/alu pipes (MUFU freed). One barrier per tile.
// ---------------------------------------------------------------------------
__global__ __launch_bounds__(128, 4) void attn_mma_kernel(const float* __restrict__ x,
                                                          float* __restrict__ out) {
    __shared__ __nv_bfloat16 Ks[2][KT][KSTRIDE];
    __shared__ __nv_bfloat16 Vs[2][KT][KSTRIDE];

    const int tid  = threadIdx.x;
    const int wid  = tid >> 5;
    const int lane = tid & 31;
    const int gid  = lane >> 2;
    const int tig  = lane & 3;
    const int lr   = lane & 7;
    const int lm   = lane >> 3;

    const int q0 = blockIdx.x * QT;
    const int h  = blockIdx.y;
    const int b  = blockIdx.z;

    const size_t hs = (size_t)NTOK * HD;
    const __nv_bfloat16* Qg = g_qkv + ((size_t)b * NHEAD + h) * hs;
    const __nv_bfloat16* Kg = g_qkv + ((size_t)(BATCH * NHEAD) + (size_t)b * NHEAD + h) * hs;
    const __nv_bfloat16* Vg = g_qkv + ((size_t)(2 * BATCH * NHEAD) + (size_t)b * NHEAD + h) * hs;

    // cp.async: 512 16B-slots per tensor per tile, 128 threads -> 4 slots each
    uint32_t ksA[4], vsA[4];
    const __nv_bfloat16 *kS[4], *vS[4];
    #pragma unroll
    for (int i = 0; i < 4; i++) {
        int slot = tid + 128 * i;
        int row = slot >> 2, c = slot & 3;
        ksA[i] = smem_u32(&Ks[0][row][c * 8]);
        vsA[i] = smem_u32(&Vs[0][row][c * 8]);
        kS[i] = Kg + (size_t)row * HD + c * 8;
        vS[i] = Vg + (size_t)row * HD + c * 8;
    }
    const uint32_t bufBytes = (uint32_t)(KT * KSTRIDE * 2);

    // prologue: prefetch tile 0 into buffer 0
    #pragma unroll
    for (int i = 0; i < 4; i++) {
        CP_ASYNC16(ksA[i], kS[i]);
        CP_ASYNC16(vsA[i], vS[i]);
    }
    CP_COMMIT();

    // Q A-fragments, two row-sets: rows 32*wid + 16*r + {gid, gid+8}
    uint32_t qA[2][2][4];
    #pragma unroll
    for (int r = 0; r < 2; r++) {
        const __nv_bfloat16* Q0 = Qg + (size_t)(q0 + 32 * wid + 16 * r + gid) * HD;
        const __nv_bfloat16* Q1 = Q0 + 8 * HD;
        #pragma unroll
        for (int s = 0; s < 2; s++) {
            qA[r][s][0] = *(const uint32_t*)(Q0 + 16 * s + 2 * tig);
            qA[r][s][1] = *(const uint32_t*)(Q1 + 16 * s + 2 * tig);
            qA[r][s][2] = *(const uint32_t*)(Q0 + 16 * s + 8 + 2 * tig);
            qA[r][s][3] = *(const uint32_t*)(Q1 + 16 * s + 8 + 2 * tig);
        }
    }

    const uint32_t ksBase = smem_u32(&Ks[0][0][0]);
    const uint32_t vsBase = smem_u32(&Vs[0][0][0]);
    const uint32_t k_lane_off = (uint32_t)(lr + 8 * (lm >> 1)) * (KSTRIDE * 2)
                              + (uint32_t)(8 * (lm & 1)) * 2;
    const uint32_t v_lane_off = (uint32_t)(lr + 8 * (lm & 1)) * (KSTRIDE * 2)
                              + (uint32_t)(8 * (lm >> 1)) * 2;

    float oacc[2][4][4] = {};
    float lsum[2][2] = {};

    for (int j = 0; j < NKT; j++) {
        const uint32_t bufOff = (uint32_t)(j & 1) * bufBytes;

        CP_WAIT0();
        __syncthreads();

        // prefetch tile j+1 into the other buffer
        if (j + 1 < NKT) {
            const size_t koff = (size_t)(j + 1) * KT * HD;
            const uint32_t other = (uint32_t)((j + 1) & 1) * bufBytes;
            #pragma unroll
            for (int i = 0; i < 4; i++) {
                CP_ASYNC16(ksA[i] + other, kS[i] + koff);
                CP_ASYNC16(vsA[i] + other, vS[i] + koff);
            }
            CP_COMMIT();
        }

        // per 16-key chunk: GEMM1 -> exp2 -> GEMM2, both row-sets
        #pragma unroll
        for (int kj = 0; kj < KT / 16; kj++) {
            float sacc[2][2][4] = {};
            #pragma unroll
            for (int s = 0; s < 2; s++) {
                uint32_t bb[4];
                LDM_X4(bb, ksBase + bufOff + k_lane_off
                             + (uint32_t)(16 * kj) * (KSTRIDE * 2)
                             + (uint32_t)(16 * s) * 2);
                #pragma unroll
                for (int r = 0; r < 2; r++) {
                    MMA_BF16(sacc[r][0], qA[r][s], bb[0], bb[1]);
                    MMA_BF16(sacc[r][1], qA[r][s], bb[2], bb[3]);
                }
            }

            uint32_t bb0[4], bb1[4];
            const uint32_t vrow = vsBase + bufOff + v_lane_off
                                + (uint32_t)(16 * kj) * (KSTRIDE * 2);
            LDM_X4_T(bb0, vrow);
            LDM_X4_T(bb1, vrow + 16 * 2);

            #pragma unroll
            for (int r = 0; r < 2; r++) {
                float e00 = fast_exp2(sacc[r][0][0]);
                float e01 = fast_exp2(sacc[r][0][1]);
                float e02 = fast_exp2(sacc[r][0][2]);
                float e03 = fast_exp2(sacc[r][0][3]);
                float e10 = fast_exp2(sacc[r][1][0]);
                float e11 = fast_exp2(sacc[r][1][1]);
                float e12 = fast_exp2(sacc[r][1][2]);
                float e13 = fast_exp2(sacc[r][1][3]);
                lsum[r][0] += (e00 + e01) + (e10 + e11);
                lsum[r][1] += (e02 + e03) + (e12 + e13);

                uint32_t a[4];
                a[0] = pack_bf16x2(e00, e01);
                a[1] = pack_bf16x2(e02, e03);
                a[2] = pack_bf16x2(e10, e11);
                a[3] = pack_bf16x2(e12, e13);

                MMA_BF16(oacc[r][0], a, bb0[0], bb0[1]);
                MMA_BF16(oacc[r][1], a, bb0[2], bb0[3]);
                MMA_BF16(oacc[r][2], a, bb1[0], bb1[1]);
                MMA_BF16(oacc[r][3], a, bb1[2], bb1[3]);
            }
        }
    }

    #pragma unroll
    for (int r = 0; r < 2; r++) {
        float l0 = lsum[r][0], l1 = lsum[r][1];
        l0 += __shfl_xor_sync(0xffffffffu, l0, 1);
        l0 += __shfl_xor_sync(0xffffffffu, l0, 2);
        l1 += __shfl_xor_sync(0xffffffffu, l1, 1);
        l1 += __shfl_xor_sync(0xffffffffu, l1, 2);
        const float inv0 = 1.0f / l0;
        const float inv1 = 1.0f / l1;

        const int tok0 = q0 + 32 * wid + 16 * r + gid;
        const size_t base0 = (size_t)b * (D_EMBED * NTOK)
                           + (size_t)tok0 * D_EMBED + h * HD;
        const size_t base1 = base0 + 8 * D_EMBED;
        #pragma unroll
        for (int nt = 0; nt < 4; nt++) {
            const int d = nt * 8 + 2 * tig;
            float2 x0 = *(const float2*)(x + base0 + d);
            float2 x1 = *(const float2*)(x + base1 + d);
            float2 o0, o1;
            o0.x = oacc[r][nt][0] * inv0 + x0.x;
            o0.y = oacc[r][nt][1] * inv0 + x0.y;
            o1.x = oacc[r][nt][2] * inv1 + x1.x;
            o1.y = oacc[r][nt][3] * inv1 + x1.y;
            *(float2*)(out + base0 + d) = o0;
            *(float2*)(out + base1 + d) = o1;
        }
    }
}

extern "C" void kernel_launch(void* const* d_in, const int* in_sizes, int n_in,
                              void* d_out, int out_size) {
    const float* x    = (const float*)d_in[0];
    const float* W    = (const float*)d_in[1];
    const float* bias = (const float*)d_in[2];
    float* out = (float*)d_out;

    dim3 gQKV(BATCH * NTOK / 128, 3);
    qkv_mma_kernel<<<gQKV, 256>>>(x, W, bias);

    dim3 gAttn(NTOK / QT, NHEAD, BATCH);
    attn_mma_kernel<<<gAttn, 128>>>(x, out);
}

// round 11
// speedup vs baseline: 1.1242x; 1.1242x over previous
#include <cuda_runtime.h>
#include <cuda_bf16.h>
#include <cstdint>
#include <math.h>

#define D_EMBED 128
#define NHEAD   4
#define HD      32
#define NTOK    4096
#define BATCH   4
#define QT      128            // queries per CTA (4 warps x 32 rows)
#define KT      64             // keys per tile
#define NKT     (NTOK / KT)

#define KSTRIDE 40             // bf16 elems per smem row (80B) -> conflict-free ldmatrix
#define QST     136            // qkv smem stride (272B rows) -> conflict-free ldmatrix

// Scratch: [part(q,k,v)][b][head][tok][hd], bf16 (Q pre-scaled by log2e/sqrt(hd))
__device__ __nv_bfloat16 g_qkv[3u * BATCH * NHEAD * NTOK * HD];

// NON-volatile: pure function, lets the compiler schedule it freely.
__device__ __forceinline__ float fast_exp2(float x) {
    float y;
    asm("ex2.approx.ftz.f32 %0, %1;" : "=f"(y) : "f"(x));
    return y;
}

__device__ __forceinline__ uint32_t smem_u32(const void* p) {
    uint32_t a;
    asm("{ .reg .u64 t; cvta.to.shared.u64 t, %1; cvt.u32.u64 %0, t; }"
        : "=r"(a) : "l"(p));
    return a;
}

__device__ __forceinline__ uint32_t pack_bf16x2(float lo, float hi) {
    uint32_t r;
    asm("cvt.rn.bf16x2.f32 %0, %1, %2;" : "=r"(r) : "f"(hi), "f"(lo));
    return r;
}

#define CP_ASYNC16(dst, src) \
    asm volatile("cp.async.ca.shared.global [%0], [%1], 16;" \
                 :: "r"(dst), "l"(src) : "memory")
#define CP_COMMIT()  asm volatile("cp.async.commit_group;" ::: "memory")
#define CP_WAIT0()   asm volatile("cp.async.wait_group 0;" ::: "memory")

// NON-volatile mma: "+f" in/out constraints carry all true dependencies;
// dropping volatile lets the compiler interleave row-sets and pipeline
// across unrolled key chunks (volatile asm is a scheduling barrier).
#define MMA_BF16(d, a, b0, b1)                                              \
    asm("mma.sync.aligned.m16n8k16.row.col.f32.bf16.bf16.f32 "              \
        "{%0,%1,%2,%3}, {%4,%5,%6,%7}, {%8,%9}, {%0,%1,%2,%3};"             \
        : "+f"((d)[0]), "+f"((d)[1]), "+f"((d)[2]), "+f"((d)[3])            \
        : "r"((a)[0]), "r"((a)[1]), "r"((a)[2]), "r"((a)[3]),               \
          "r"(b0), "r"(b1))

#define LDM_X4(r, addr)                                                     \
    asm volatile("ldmatrix.sync.aligned.m8n8.x4.shared.b16 "                \
                 "{%0,%1,%2,%3}, [%4];"                                     \
                 : "=r"((r)[0]), "=r"((r)[1]), "=r"((r)[2]), "=r"((r)[3])   \
                 : "r"(addr))

#define LDM_X4_T(r, addr)                                                   \
    asm volatile("ldmatrix.sync.aligned.m8n8.x4.trans.shared.b16 "          \
                 "{%0,%1,%2,%3}, [%4];"                                     \
                 : "=r"((r)[0]), "=r"((r)[1]), "=r"((r)[2]), "=r"((r)[3])   \
                 : "r"(addr))

// ---------------------------------------------------------------------------
// QKV projection with bf16 tensor cores (unchanged from round 9).
// ---------------------------------------------------------------------------
__global__ __launch_bounds__(256) void qkv_mma_kernel(const float* __restrict__ x,
                                                      const float* __restrict__ W,
                                                      const float* __restrict__ bias) {
    __shared__ __nv_bfloat16 As[32][QST];   // [k][token]
    __shared__ __nv_bfloat16 Ws[32][QST];   // [k][col]

    const int tid  = threadIdx.x;
    const int wid  = tid >> 5;
    const int lane = tid & 31;
    const int gid  = lane >> 2;
    const int tig  = lane & 3;
    const int lr   = lane & 7;
    const int lm   = lane >> 3;

    const int m0   = blockIdx.x * 128;
    const int b    = m0 / NTOK;
    const int pix0 = m0 % NTOK;
    const int part = blockIdx.y;
    const int col0 = part * 128;

    const float* xb = x + (size_t)b * D_EMBED * NTOK;

    const int mwarp = 32 * (wid >> 1);
    const int nwarp = 64 * (wid & 1);

    const uint32_t aBase = smem_u32(&As[0][0]);
    const uint32_t wBase = smem_u32(&Ws[0][0]);
    const uint32_t ROWB = QST * 2;
    const uint32_t a_lane = (uint32_t)(lr + 8 * (lm >> 1)) * ROWB
                          + (uint32_t)(8 * (lm & 1)) * 2;
    const uint32_t b_lane = (uint32_t)(lr + 8 * (lm & 1)) * ROWB
                          + (uint32_t)(8 * (lm >> 1)) * 2;

    float oacc[2][8][4] = {};

    for (int kc = 0; kc < 4; kc++) {
        const int k0 = kc * 32;
        __syncthreads();
        #pragma unroll
        for (int i = 0; i < 4; i++) {
            int idx = tid + i * 256;
            int row = idx >> 5, p4 = idx & 31;
            float4 xa = *(const float4*)(xb + (size_t)(k0 + row) * NTOK + pix0 + 4 * p4);
            float4 wa = *(const float4*)(W + (size_t)(k0 + row) * 384 + col0 + 4 * p4);
            uint2 xv = { pack_bf16x2(xa.x, xa.y), pack_bf16x2(xa.z, xa.w) };
            uint2 wv = { pack_bf16x2(wa.x, wa.y), pack_bf16x2(wa.z, wa.w) };
            *(uint2*)&As[row][4 * p4] = xv;
            *(uint2*)&Ws[row][4 * p4] = wv;
        }
        __syncthreads();

        #pragma unroll
        for (int s = 0; s < 2; s++) {
            uint32_t aF[2][4];
            #pragma unroll
            for (int r = 0; r < 2; r++)
                LDM_X4_T(aF[r], aBase + a_lane + (uint32_t)(16 * s) * ROWB
                                 + (uint32_t)(mwarp + 16 * r) * 2);
            #pragma unroll
            for (int g2 = 0; g2 < 4; g2++) {
                uint32_t bF[4];
                LDM_X4_T(bF, wBase + b_lane + (uint32_t)(16 * s) * ROWB
                               + (uint32_t)(nwarp + 16 * g2) * 2);
                #pragma unroll
                for (int r = 0; r < 2; r++) {
                    MMA_BF16(oacc[r][2 * g2],     aF[r], bF[0], bF[1]);
                    MMA_BF16(oacc[r][2 * g2 + 1], aF[r], bF[2], bF[3]);
                }
            }
        }
    }

    const float qs = (part == 0) ? 0.17677669529663687f * 1.4426950408889634f : 1.0f;
    #pragma unroll
    for (int r = 0; r < 2; r++) {
        const int tok = pix0 + mwarp + 16 * r + gid;
        #pragma unroll
        for (int nt = 0; nt < 8; nt++) {
            const int col = nwarp + nt * 8 + 2 * tig;
            const int head = col >> 5;
            const int d    = col & 31;
            const float bx = bias[col0 + col];
            const float by = bias[col0 + col + 1];
            __nv_bfloat16* dst =
                g_qkv + ((((size_t)part * BATCH + b) * NHEAD + head) * NTOK + tok) * HD + d;
            *(uint32_t*)dst =
                pack_bf16x2((oacc[r][nt][0] + bx) * qs, (oacc[r][nt][1] + by) * qs);
            *(uint32_t*)(dst + 8 * HD) =
                pack_bf16x2((oacc[r][nt][2] + bx) * qs, (oacc[r][nt][3] + by) * qs);
        }
    }
}

// ---------------------------------------------------------------------------
// Flash attention, bf16 mma.m16n8k16 + ldmatrix + cp.async double buffering.
// 4 warps x 32 query rows; 64-key tiles; MUFU exp2; non-volatile mma so the
// compiler can interleave row-sets / pipeline across chunks.
// ---------------------------------------------------------------------------
__global__ __launch_bounds__(128, 4) void attn_mma_kernel(const float* __restrict__ x,
                                                          float* __restrict__ out) {
    __shared__ __nv_bfloat16 Ks[2][KT][KSTRIDE];
    __shared__ __nv_bfloat16 Vs[2][KT][KSTRIDE];

    const int tid  = threadIdx.x;
    const int wid  = tid >> 5;
    const int lane = tid & 31;
    const int gid  = lane >> 2;
    const int tig  = lane & 3;
    const int lr   = lane & 7;
    const int lm   = lane >> 3;

    const int q0 = blockIdx.x * QT;
    const int h  = blockIdx.y;
    const int b  = blockIdx.z;

    const size_t hs = (size_t)NTOK * HD;
    const __nv_bfloat16* Qg = g_qkv + ((size_t)b * NHEAD + h) * hs;
    const __nv_bfloat16* Kg = g_qkv + ((size_t)(BATCH * NHEAD) + (size_t)b * NHEAD + h) * hs;
    const __nv_bfloat16* Vg = g_qkv + ((size_t)(2 * BATCH * NHEAD) + (size_t)b * NHEAD + h) * hs;

    const int s0row = tid >> 2, s0c = tid & 3;
    const int s1row = (tid + 128) >> 2, s1c = tid & 3;
    const uint32_t ksA0 = smem_u32(&Ks[0][s0row][s0c * 8]);
    const uint32_t ksA1 = smem_u32(&Ks[0][s1row][s1c * 8]);
    const uint32_t vsA0 = smem_u32(&Vs[0][s0row][s0c * 8]);
    const uint32_t vsA1 = smem_u32(&Vs[0][s1row][s1c * 8]);
    const uint32_t bufBytes = (uint32_t)(KT * KSTRIDE * 2);
    const __nv_bfloat16* kS0 = Kg + (size_t)s0row * HD + s0c * 8;
    const __nv_bfloat16* kS1 = Kg + (size_t)s1row * HD + s1c * 8;
    const __nv_bfloat16* vS0 = Vg + (size_t)s0row * HD + s0c * 8;
    const __nv_bfloat16* vS1 = Vg + (size_t)s1row * HD + s1c * 8;

    CP_ASYNC16(ksA0, kS0);
    CP_ASYNC16(ksA1, kS1);
    CP_ASYNC16(vsA0, vS0);
    CP_ASYNC16(vsA1, vS1);
    CP_COMMIT();

    uint32_t qA[2][2][4];
    #pragma unroll
    for (int r = 0; r < 2; r++) {
        const __nv_bfloat16* Q0 = Qg + (size_t)(q0 + 32 * wid + 16 * r + gid) * HD;
        const __nv_bfloat16* Q1 = Q0 + 8 * HD;
        #pragma unroll
        for (int s = 0; s < 2; s++) {
            qA[r][s][0] = *(const uint32_t*)(Q0 + 16 * s + 2 * tig);
            qA[r][s][1] = *(const uint32_t*)(Q1 + 16 * s + 2 * tig);
            qA[r][s][2] = *(const uint32_t*)(Q0 + 16 * s + 8 + 2 * tig);
            qA[r][s][3] = *(const uint32_t*)(Q1 + 16 * s + 8 + 2 * tig);
        }
    }

    const uint32_t ksBase = smem_u32(&Ks[0][0][0]);
    const uint32_t vsBase = smem_u32(&Vs[0][0][0]);
    const uint32_t k_lane_off = (uint32_t)(lr + 8 * (lm >> 1)) * (KSTRIDE * 2)
                              + (uint32_t)(8 * (lm & 1)) * 2;
    const uint32_t v_lane_off = (uint32_t)(lr + 8 * (lm & 1)) * (KSTRIDE * 2)
                              + (uint32_t)(8 * (lm >> 1)) * 2;

    float oacc[2][4][4] = {};
    float lsum[2][2] = {};

    for (int j = 0; j < NKT; j++) {
        const uint32_t bufOff = (uint32_t)(j & 1) * bufBytes;

        CP_WAIT0();
        __syncthreads();

        if (j + 1 < NKT) {
            const size_t koff = (size_t)(j + 1) * KT * HD;
            const uint32_t other = (uint32_t)((j + 1) & 1) * bufBytes;
            CP_ASYNC16(ksA0 + other, kS0 + koff);
            CP_ASYNC16(ksA1 + other, kS1 + koff);
            CP_ASYNC16(vsA0 + other, vS0 + koff);
            CP_ASYNC16(vsA1 + other, vS1 + koff);
            CP_COMMIT();
        }

        #pragma unroll
        for (int kj = 0; kj < 4; kj++) {
            float sacc[2][2][4] = {};
            #pragma unroll
            for (int s = 0; s < 2; s++) {
                uint32_t bb[4];
                LDM_X4(bb, ksBase + bufOff + k_lane_off
                             + (uint32_t)(16 * kj) * (KSTRIDE * 2)
                             + (uint32_t)(16 * s) * 2);
                #pragma unroll
                for (int r = 0; r < 2; r++) {
                    MMA_BF16(sacc[r][0], qA[r][s], bb[0], bb[1]);
                    MMA_BF16(sacc[r][1], qA[r][s], bb[2], bb[3]);
                }
            }

            uint32_t bb0[4], bb1[4];
            const uint32_t vrow = vsBase + bufOff + v_lane_off
                                + (uint32_t)(16 * kj) * (KSTRIDE * 2);
            LDM_X4_T(bb0, vrow);
            LDM_X4_T(bb1, vrow + 16 * 2);

            #pragma unroll
            for (int r = 0; r < 2; r++) {
                float e00 = fast_exp2(sacc[r][0][0]);
                float e01 = fast_exp2(sacc[r][0][1]);
                float e02 = fast_exp2(sacc[r][0][2]);
                float e03 = fast_exp2(sacc[r][0][3]);
                float e10 = fast_exp2(sacc[r][1][0]);
                float e11 = fast_exp2(sacc[r][1][1]);
                float e12 = fast_exp2(sacc[r][1][2]);
                float e13 = fast_exp2(sacc[r][1][3]);
                lsum[r][0] += (e00 + e01) + (e10 + e11);
                lsum[r][1] += (e02 + e03) + (e12 + e13);

                uint32_t a[4];
                a[0] = pack_bf16x2(e00, e01);
                a[1] = pack_bf16x2(e02, e03);
                a[2] = pack_bf16x2(e10, e11);
                a[3] = pack_bf16x2(e12, e13);

                MMA_BF16(oacc[r][0], a, bb0[0], bb0[1]);
                MMA_BF16(oacc[r][1], a, bb0[2], bb0[3]);
                MMA_BF16(oacc[r][2], a, bb1[0], bb1[1]);
                MMA_BF16(oacc[r][3], a, bb1[2], bb1[3]);
            }
        }
    }

    #pragma unroll
    for (int r = 0; r < 2; r++) {
        float l0 = lsum[r][0], l1 = lsum[r][1];
        l0 += __shfl_xor_sync(0xffffffffu, l0, 1);
        l0 += __shfl_xor_sync(0xffffffffu, l0, 2);
        l1 += __shfl_xor_sync(0xffffffffu, l1, 1);
        l1 += __shfl_xor_sync(0xffffffffu, l1, 2);
        const float inv0 = 1.0f / l0;
        const float inv1 = 1.0f / l1;

        const int tok0 = q0 + 32 * wid + 16 * r + gid;
        const size_t base0 = (size_t)b * (D_EMBED * NTOK)
                           + (size_t)tok0 * D_EMBED + h * HD;
        const size_t base1 = base0 + 8 * D_EMBED;
        #pragma unroll
        for (int nt = 0; nt < 4; nt++) {
            const int d = nt * 8 + 2 * tig;
            float2 x0 = *(const float2*)(x + base0 + d);
            float2 x1 = *(const float2*)(x + base1 + d);
            float2 o0, o1;
            o0.x = oacc[r][nt][0] * inv0 + x0.x;
            o0.y = oacc[r][nt][1] * inv0 + x0.y;
            o1.x = oacc[r][nt][2] * inv1 + x1.x;
            o1.y = oacc[r][nt][3] * inv1 + x1.y;
            *(float2*)(out + base0 + d) = o0;
            *(float2*)(out + base1 + d) = o1;
        }
    }
}

extern "C" void kernel_launch(void* const* d_in, const int* in_sizes, int n_in,
                              void* d_out, int out_size) {
    const float* x    = (const float*)d_in[0];
    const float* W    = (const float*)d_in[1];
    const float* bias = (const float*)d_in[2];
    float* out = (float*)d_out;

    dim3 gQKV(BATCH * NTOK / 128, 3);
    qkv_mma_kernel<<<gQKV, 256>>>(x, W, bias);

    dim3 gAttn(NTOK / QT, NHEAD, BATCH);
    attn_mma_kernel<<<gAttn, 128>>>(x, out);
}